// round 1
// baseline (speedup 1.0000x reference)
#include <cuda_runtime.h>
#include <math.h>

#define BB 4
#define TT 1024
#define DD 1024
#define HH 16
#define HSS 64

// Scratch (no cudaMalloc allowed)
__device__ float g_q[BB*HH*TT*HSS];
__device__ float g_k[BB*HH*TT*HSS];
__device__ float g_v[BB*HH*TT*HSS];
__device__ float g_att[BB*TT*DD];   // concat-head attention output [B*T, H*HS]

// ---------------------------------------------------------------------------
// Generic 128x64 GEMM tile: C[128,64] = A[128,K] @ Bm[K,64] (+bias)
// 256 threads, each computes 8x4 micro-tile. BK = 32.
// ---------------------------------------------------------------------------
__device__ __forceinline__ void gemm_tile_128x64(
    const float* __restrict__ A, int lda,
    const float* __restrict__ Bm, int ldb,
    float* __restrict__ C, int ldc,
    int K, const float* __restrict__ bias)
{
    __shared__ float As[32 * 132];   // [k][m], stride 132 (mult of 4, low-conflict)
    __shared__ float Bs[32 * 64];    // [k][n]

    const int tid = threadIdx.x;
    const int tx = tid & 15;         // 0..15 -> n
    const int ty = tid >> 4;         // 0..15 -> m
    const int m0 = ty * 8;
    const int n0 = tx * 4;

    float acc[8][4];
#pragma unroll
    for (int i = 0; i < 8; i++)
#pragma unroll
        for (int j = 0; j < 4; j++) acc[i][j] = 0.f;

    for (int k0 = 0; k0 < K; k0 += 32) {
        // Load A tile [128 x 32] transposed into As[k][m]
#pragma unroll
        for (int i = 0; i < 4; i++) {
            int l = tid + i * 256;           // 0..1023
            int row = l >> 3;                // 0..127
            int k4  = l & 7;                 // 0..7
            float4 va = *reinterpret_cast<const float4*>(&A[(size_t)row * lda + k0 + k4 * 4]);
            As[(k4 * 4 + 0) * 132 + row] = va.x;
            As[(k4 * 4 + 1) * 132 + row] = va.y;
            As[(k4 * 4 + 2) * 132 + row] = va.z;
            As[(k4 * 4 + 3) * 132 + row] = va.w;
        }
        // Load B tile [32 x 64]
#pragma unroll
        for (int i = 0; i < 2; i++) {
            int l = tid + i * 256;           // 0..511
            int kr = l >> 4;                 // 0..31
            int n4 = l & 15;                 // 0..15
            float4 vb = *reinterpret_cast<const float4*>(&Bm[(size_t)(k0 + kr) * ldb + n4 * 4]);
            *reinterpret_cast<float4*>(&Bs[kr * 64 + n4 * 4]) = vb;
        }
        __syncthreads();

#pragma unroll
        for (int kk = 0; kk < 32; kk++) {
            float4 a0 = *reinterpret_cast<const float4*>(&As[kk * 132 + m0]);
            float4 a1 = *reinterpret_cast<const float4*>(&As[kk * 132 + m0 + 4]);
            float4 b  = *reinterpret_cast<const float4*>(&Bs[kk * 64 + n0]);
            float av[8] = {a0.x, a0.y, a0.z, a0.w, a1.x, a1.y, a1.z, a1.w};
            float bv[4] = {b.x, b.y, b.z, b.w};
#pragma unroll
            for (int i = 0; i < 8; i++)
#pragma unroll
                for (int j = 0; j < 4; j++)
                    acc[i][j] = fmaf(av[i], bv[j], acc[i][j]);
        }
        __syncthreads();
    }

#pragma unroll
    for (int i = 0; i < 8; i++) {
#pragma unroll
        for (int j = 0; j < 4; j++) {
            float v = acc[i][j];
            if (bias) v += bias[n0 + j];
            C[(size_t)(m0 + i) * ldc + n0 + j] = v;
        }
    }
}

// ---------------------------------------------------------------------------
// QKV projection: for each (b, h, {q,k,v}), C[T,HS] = x_b[T,D] @ W_h[D,HS]
// grid: (T/128, H, B*3)
// ---------------------------------------------------------------------------
__global__ void qkv_kernel(const float* __restrict__ x,
                           const float* __restrict__ Wq,
                           const float* __restrict__ Wk,
                           const float* __restrict__ Wv)
{
    const int mt = blockIdx.x;
    const int h  = blockIdx.y;
    const int z  = blockIdx.z;
    const int b  = z / 3;
    const int which = z % 3;

    const float* A = x + (size_t)b * TT * DD + (size_t)mt * 128 * DD;
    const float* W = (which == 0 ? Wq : which == 1 ? Wk : Wv) + (size_t)h * DD * HSS;
    float* Cb = (which == 0 ? g_q : which == 1 ? g_k : g_v)
                + ((size_t)(b * HH + h) * TT + (size_t)mt * 128) * HSS;

    gemm_tile_128x64(A, DD, W, HSS, Cb, HSS, DD, nullptr);
}

// ---------------------------------------------------------------------------
// Causal flash attention, fp32. One block per (q-tile of 64 rows, b*H+h).
// 256 threads (16x16), each owns a 4x4 micro-tile of S / O.
// ---------------------------------------------------------------------------
#define ATTN_SMEM ((64*68 + 64*68 + 64*64) * 4)

__global__ void attn_kernel()
{
    extern __shared__ float sm[];
    float* Qs = sm;               // [e][r] stride 68
    float* Ks = Qs + 64 * 68;     // [e][c] stride 68; reused as Ps[c][r]
    float* Vs = Ks + 64 * 68;     // [kk][n] stride 64

    const int it = blockIdx.x;    // query tile
    const int bh = blockIdx.y;    // b*H + h
    const int b = bh / HH, h = bh % HH;

    const float* Q  = g_q + (size_t)bh * TT * HSS + (size_t)it * 64 * HSS;
    const float* Kg = g_k + (size_t)bh * TT * HSS;
    const float* Vg = g_v + (size_t)bh * TT * HSS;

    const int tid = threadIdx.x;
    const int tx = tid & 15;
    const int ty = tid >> 4;
    const int r0 = ty * 4;        // micro rows (queries)
    const int n0 = tx * 4;        // micro cols (keys for S; out-dim for PV)

    // Load Q tile transposed: Qs[e][r]
#pragma unroll
    for (int i = 0; i < 4; i++) {
        int l = tid + i * 256;        // 0..1023
        int row = l >> 4;             // 0..63
        int e4  = l & 15;             // 0..15
        float4 v = *reinterpret_cast<const float4*>(&Q[(size_t)row * HSS + e4 * 4]);
        Qs[(e4 * 4 + 0) * 68 + row] = v.x;
        Qs[(e4 * 4 + 1) * 68 + row] = v.y;
        Qs[(e4 * 4 + 2) * 68 + row] = v.z;
        Qs[(e4 * 4 + 3) * 68 + row] = v.w;
    }

    float m_r[4], l_r[4], acc[4][4];
#pragma unroll
    for (int i = 0; i < 4; i++) {
        m_r[i] = -1e30f;
        l_r[i] = 0.f;
#pragma unroll
        for (int j = 0; j < 4; j++) acc[i][j] = 0.f;
    }

    for (int jt = 0; jt <= it; jt++) {
        __syncthreads();   // prior-iter PV reads done; also covers Q-store visibility
        const float* Kt = Kg + (size_t)jt * 64 * HSS;
        const float* Vt = Vg + (size_t)jt * 64 * HSS;
#pragma unroll
        for (int i = 0; i < 4; i++) {
            int l = tid + i * 256;
            int row = l >> 4;
            int e4  = l & 15;
            float4 kv = *reinterpret_cast<const float4*>(&Kt[(size_t)row * HSS + e4 * 4]);
            Ks[(e4 * 4 + 0) * 68 + row] = kv.x;
            Ks[(e4 * 4 + 1) * 68 + row] = kv.y;
            Ks[(e4 * 4 + 2) * 68 + row] = kv.z;
            Ks[(e4 * 4 + 3) * 68 + row] = kv.w;
            float4 vv = *reinterpret_cast<const float4*>(&Vt[(size_t)row * HSS + e4 * 4]);
            *reinterpret_cast<float4*>(&Vs[row * 64 + e4 * 4]) = vv;
        }
        __syncthreads();

        // S = (Q K^T) * scale
        float s[4][4];
#pragma unroll
        for (int i = 0; i < 4; i++)
#pragma unroll
            for (int j = 0; j < 4; j++) s[i][j] = 0.f;

#pragma unroll 8
        for (int e = 0; e < 64; e++) {
            float4 q = *reinterpret_cast<const float4*>(&Qs[e * 68 + r0]);
            float4 k = *reinterpret_cast<const float4*>(&Ks[e * 68 + n0]);
            float qv[4] = {q.x, q.y, q.z, q.w};
            float kv[4] = {k.x, k.y, k.z, k.w};
#pragma unroll
            for (int i = 0; i < 4; i++)
#pragma unroll
                for (int j = 0; j < 4; j++)
                    s[i][j] = fmaf(qv[i], kv[j], s[i][j]);
        }

        const float scale = 0.125f;   // HS^-0.5
#pragma unroll
        for (int i = 0; i < 4; i++)
#pragma unroll
            for (int j = 0; j < 4; j++) s[i][j] *= scale;

        if (jt == it) {  // causal mask on diagonal tile
#pragma unroll
            for (int i = 0; i < 4; i++)
#pragma unroll
                for (int j = 0; j < 4; j++)
                    if (n0 + j > r0 + i) s[i][j] = -1e30f;
        }

        // online softmax update
        float p[4][4];
#pragma unroll
        for (int i = 0; i < 4; i++) {
            float mx = fmaxf(fmaxf(s[i][0], s[i][1]), fmaxf(s[i][2], s[i][3]));
#pragma unroll
            for (int o = 1; o < 16; o <<= 1)
                mx = fmaxf(mx, __shfl_xor_sync(0xffffffffu, mx, o));
            float mnew = fmaxf(m_r[i], mx);
            float sc = __expf(m_r[i] - mnew);
            float rs = 0.f;
#pragma unroll
            for (int j = 0; j < 4; j++) {
                p[i][j] = __expf(s[i][j] - mnew);
                rs += p[i][j];
            }
#pragma unroll
            for (int o = 1; o < 16; o <<= 1)
                rs += __shfl_xor_sync(0xffffffffu, rs, o);
            l_r[i] = l_r[i] * sc + rs;
#pragma unroll
            for (int j = 0; j < 4; j++) acc[i][j] *= sc;
            m_r[i] = mnew;
        }

        __syncthreads();  // all Ks reads done before overwriting with P
        // write P into Ks buffer: Ps[c][r], stride 68
#pragma unroll
        for (int j = 0; j < 4; j++)
#pragma unroll
            for (int i = 0; i < 4; i++)
                Ks[(n0 + j) * 68 + (r0 + i)] = p[i][j];
        __syncthreads();

        // O += P @ V
#pragma unroll 8
        for (int kk = 0; kk < 64; kk++) {
            float4 pv = *reinterpret_cast<const float4*>(&Ks[kk * 68 + r0]);
            float4 vv = *reinterpret_cast<const float4*>(&Vs[kk * 64 + n0]);
            float pr[4] = {pv.x, pv.y, pv.z, pv.w};
            float vn[4] = {vv.x, vv.y, vv.z, vv.w};
#pragma unroll
            for (int i = 0; i < 4; i++)
#pragma unroll
                for (int j = 0; j < 4; j++)
                    acc[i][j] = fmaf(pr[i], vn[j], acc[i][j]);
        }
    }

    // normalize + write to concat-head layout g_att[b, t, h*HS + e]
#pragma unroll
    for (int i = 0; i < 4; i++) {
        float inv = 1.f / l_r[i];
        size_t row = (size_t)b * TT + (size_t)it * 64 + r0 + i;
#pragma unroll
        for (int j = 0; j < 4; j++)
            g_att[row * DD + (size_t)h * HSS + n0 + j] = acc[i][j] * inv;
    }
}

// ---------------------------------------------------------------------------
// Output projection: out[B*T, D] = g_att[B*T, D] @ Wo[D, D] + bo
// grid: (B*T/128, D/64)
// ---------------------------------------------------------------------------
__global__ void proj_kernel(const float* __restrict__ Wo,
                            const float* __restrict__ bo,
                            float* __restrict__ out)
{
    const int mt = blockIdx.x;
    const int nt = blockIdx.y;
    const float* A  = g_att + (size_t)mt * 128 * DD;
    const float* Bm = Wo + (size_t)nt * 64;
    float* C = out + (size_t)mt * 128 * DD + (size_t)nt * 64;
    gemm_tile_128x64(A, DD, Bm, DD, C, DD, DD, bo + nt * 64);
}

extern "C" void kernel_launch(void* const* d_in, const int* in_sizes, int n_in,
                              void* d_out, int out_size)
{
    const float* x  = (const float*)d_in[0];
    const float* Wq = (const float*)d_in[1];
    const float* Wk = (const float*)d_in[2];
    const float* Wv = (const float*)d_in[3];
    const float* Wo = (const float*)d_in[4];
    const float* bo = (const float*)d_in[5];
    float* out = (float*)d_out;

    cudaFuncSetAttribute(attn_kernel,
                         cudaFuncAttributeMaxDynamicSharedMemorySize, ATTN_SMEM);

    dim3 g1(TT / 128, HH, BB * 3);
    qkv_kernel<<<g1, 256>>>(x, Wq, Wk, Wv);

    dim3 g2(TT / 64, BB * HH);
    attn_kernel<<<g2, 256, ATTN_SMEM>>>();

    dim3 g3((BB * TT) / 128, DD / 64);
    proj_kernel<<<g3, 256>>>(Wo, bo, out);
}

// round 2
// speedup vs baseline: 2.8927x; 2.8927x over previous
#include <cuda_runtime.h>
#include <math.h>

#define BB 4
#define TT 1024
#define DD 1024
#define HH 16
#define HSS 64

// Scratch (no cudaMalloc allowed)
__device__ float g_q[BB*HH*TT*HSS];
__device__ float g_k[BB*HH*TT*HSS];
__device__ float g_v[BB*HH*TT*HSS];
__device__ float g_att[BB*TT*DD];   // concat-head attention output [B*T, H*HS]

// ---------------------------------------------------------------------------
// tf32 helpers
// ---------------------------------------------------------------------------
__device__ __forceinline__ unsigned f2tf(float f) {
    unsigned r;
    asm("cvt.rna.tf32.f32 %0, %1;" : "=r"(r) : "f"(f));
    return r;
}

__device__ __forceinline__ void mma8(float* d, const unsigned* a, const unsigned* b) {
    asm volatile(
        "mma.sync.aligned.m16n8k8.row.col.f32.tf32.tf32.f32 "
        "{%0,%1,%2,%3}, {%4,%5,%6,%7}, {%8,%9}, {%0,%1,%2,%3};"
        : "+f"(d[0]), "+f"(d[1]), "+f"(d[2]), "+f"(d[3])
        : "r"(a[0]), "r"(a[1]), "r"(a[2]), "r"(a[3]),
          "r"(b[0]), "r"(b[1]));
}

// ---------------------------------------------------------------------------
// Tensor-core GEMM tile: C[128,64] = A[128,K] @ Bm[K,64] (+bias), tf32 mma.
// 256 threads = 8 warps in 4(m) x 2(n); warp tile 32x32; frag m16n8k8.
// A smem: [m][36]  (bank = (4m+k)%32 -> conflict-free frag loads)
// B smem: [k][72]  (bank = (8k+n)%32 -> conflict-free frag loads)
// ---------------------------------------------------------------------------
__device__ __forceinline__ void gemm_mma_128x64(
    const float* __restrict__ A, int lda,
    const float* __restrict__ Bm, int ldb,
    float* __restrict__ C, int ldc,
    int K, const float* __restrict__ bias)
{
    __shared__ unsigned As[128 * 36];
    __shared__ unsigned Bs[32 * 72];

    const int tid  = threadIdx.x;
    const int lane = tid & 31;
    const int warp = tid >> 5;
    const int wm   = warp >> 1;     // 0..3
    const int wn   = warp & 1;      // 0..1
    const int lq   = lane >> 2;     // 0..7
    const int lr   = lane & 3;      // 0..3

    float acc[2][4][4];
#pragma unroll
    for (int mf = 0; mf < 2; mf++)
#pragma unroll
        for (int nf = 0; nf < 4; nf++)
#pragma unroll
            for (int j = 0; j < 4; j++) acc[mf][nf][j] = 0.f;

    for (int k0 = 0; k0 < K; k0 += 32) {
        // Load A tile [128 x 32] -> As[m][k] (tf32-converted)
#pragma unroll
        for (int i = 0; i < 4; i++) {
            int l   = tid + i * 256;          // 0..1023
            int row = l >> 3;                 // 0..127
            int k4  = l & 7;                  // 0..7
            float4 v = *reinterpret_cast<const float4*>(&A[(size_t)row * lda + k0 + k4 * 4]);
            unsigned* p = &As[row * 36 + k4 * 4];
            p[0] = f2tf(v.x); p[1] = f2tf(v.y); p[2] = f2tf(v.z); p[3] = f2tf(v.w);
        }
        // Load B tile [32 x 64] -> Bs[k][n]
#pragma unroll
        for (int i = 0; i < 2; i++) {
            int l  = tid + i * 256;           // 0..511
            int kr = l >> 4;                  // 0..31
            int n4 = l & 15;                  // 0..15
            float4 v = *reinterpret_cast<const float4*>(&Bm[(size_t)(k0 + kr) * ldb + n4 * 4]);
            unsigned* p = &Bs[kr * 72 + n4 * 4];
            p[0] = f2tf(v.x); p[1] = f2tf(v.y); p[2] = f2tf(v.z); p[3] = f2tf(v.w);
        }
        __syncthreads();

#pragma unroll
        for (int kk = 0; kk < 4; kk++) {
            const int kc = kk * 8 + lr;
            unsigned a[2][4], b[4][2];
#pragma unroll
            for (int mf = 0; mf < 2; mf++) {
                int mr = wm * 32 + mf * 16 + lq;
                a[mf][0] = As[mr * 36 + kc];
                a[mf][1] = As[(mr + 8) * 36 + kc];
                a[mf][2] = As[mr * 36 + kc + 4];
                a[mf][3] = As[(mr + 8) * 36 + kc + 4];
            }
#pragma unroll
            for (int nf = 0; nf < 4; nf++) {
                int nc = wn * 32 + nf * 8 + lq;
                b[nf][0] = Bs[kc * 72 + nc];
                b[nf][1] = Bs[(kc + 4) * 72 + nc];
            }
#pragma unroll
            for (int mf = 0; mf < 2; mf++)
#pragma unroll
                for (int nf = 0; nf < 4; nf++)
                    mma8(acc[mf][nf], a[mf], b[nf]);
        }
        __syncthreads();
    }

    // Epilogue: c frag layout m16n8 -> rows lq, lq+8; cols 2*lr, 2*lr+1
#pragma unroll
    for (int mf = 0; mf < 2; mf++) {
#pragma unroll
        for (int nf = 0; nf < 4; nf++) {
            int row = wm * 32 + mf * 16 + lq;
            int col = wn * 32 + nf * 8 + 2 * lr;
            float b0 = bias ? bias[col] : 0.f;
            float b1 = bias ? bias[col + 1] : 0.f;
            C[(size_t)row * ldc + col]           = acc[mf][nf][0] + b0;
            C[(size_t)row * ldc + col + 1]       = acc[mf][nf][1] + b1;
            C[(size_t)(row + 8) * ldc + col]     = acc[mf][nf][2] + b0;
            C[(size_t)(row + 8) * ldc + col + 1] = acc[mf][nf][3] + b1;
        }
    }
}

// ---------------------------------------------------------------------------
// QKV projection: for each (b, h, {q,k,v}), C[T,HS] = x_b[T,D] @ W_h[D,HS]
// grid: (T/128, H, B*3)
// ---------------------------------------------------------------------------
__global__ void qkv_kernel(const float* __restrict__ x,
                           const float* __restrict__ Wq,
                           const float* __restrict__ Wk,
                           const float* __restrict__ Wv)
{
    const int mt = blockIdx.x;
    const int h  = blockIdx.y;
    const int z  = blockIdx.z;
    const int b  = z / 3;
    const int which = z % 3;

    const float* A = x + (size_t)b * TT * DD + (size_t)mt * 128 * DD;
    const float* W = (which == 0 ? Wq : which == 1 ? Wk : Wv) + (size_t)h * DD * HSS;
    float* Cb = (which == 0 ? g_q : which == 1 ? g_k : g_v)
                + ((size_t)(b * HH + h) * TT + (size_t)mt * 128) * HSS;

    gemm_mma_128x64(A, DD, W, HSS, Cb, HSS, DD, nullptr);
}

// ---------------------------------------------------------------------------
// Causal flash attention, fp32. One block per (q-tile of 64 rows, b*H+h).
// 256 threads (16x16), each owns a 4x4 micro-tile of S / O.
// ---------------------------------------------------------------------------
#define ATTN_SMEM ((64*68 + 64*68 + 64*64) * 4)

__global__ void attn_kernel()
{
    extern __shared__ float sm[];
    float* Qs = sm;               // [e][r] stride 68
    float* Ks = Qs + 64 * 68;     // [e][c] stride 68; reused as Ps[c][r]
    float* Vs = Ks + 64 * 68;     // [kk][n] stride 64

    const int it = blockIdx.x;    // query tile
    const int bh = blockIdx.y;    // b*H + h
    const int b = bh / HH, h = bh % HH;

    const float* Q  = g_q + (size_t)bh * TT * HSS + (size_t)it * 64 * HSS;
    const float* Kg = g_k + (size_t)bh * TT * HSS;
    const float* Vg = g_v + (size_t)bh * TT * HSS;

    const int tid = threadIdx.x;
    const int tx = tid & 15;
    const int ty = tid >> 4;
    const int r0 = ty * 4;        // micro rows (queries)
    const int n0 = tx * 4;        // micro cols (keys for S; out-dim for PV)

    // Load Q tile transposed: Qs[e][r]
#pragma unroll
    for (int i = 0; i < 4; i++) {
        int l = tid + i * 256;        // 0..1023
        int row = l >> 4;             // 0..63
        int e4  = l & 15;             // 0..15
        float4 v = *reinterpret_cast<const float4*>(&Q[(size_t)row * HSS + e4 * 4]);
        Qs[(e4 * 4 + 0) * 68 + row] = v.x;
        Qs[(e4 * 4 + 1) * 68 + row] = v.y;
        Qs[(e4 * 4 + 2) * 68 + row] = v.z;
        Qs[(e4 * 4 + 3) * 68 + row] = v.w;
    }

    float m_r[4], l_r[4], acc[4][4];
#pragma unroll
    for (int i = 0; i < 4; i++) {
        m_r[i] = -1e30f;
        l_r[i] = 0.f;
#pragma unroll
        for (int j = 0; j < 4; j++) acc[i][j] = 0.f;
    }

    for (int jt = 0; jt <= it; jt++) {
        __syncthreads();   // prior-iter PV reads done; also covers Q-store visibility
        const float* Kt = Kg + (size_t)jt * 64 * HSS;
        const float* Vt = Vg + (size_t)jt * 64 * HSS;
#pragma unroll
        for (int i = 0; i < 4; i++) {
            int l = tid + i * 256;
            int row = l >> 4;
            int e4  = l & 15;
            float4 kv = *reinterpret_cast<const float4*>(&Kt[(size_t)row * HSS + e4 * 4]);
            Ks[(e4 * 4 + 0) * 68 + row] = kv.x;
            Ks[(e4 * 4 + 1) * 68 + row] = kv.y;
            Ks[(e4 * 4 + 2) * 68 + row] = kv.z;
            Ks[(e4 * 4 + 3) * 68 + row] = kv.w;
            float4 vv = *reinterpret_cast<const float4*>(&Vt[(size_t)row * HSS + e4 * 4]);
            *reinterpret_cast<float4*>(&Vs[row * 64 + e4 * 4]) = vv;
        }
        __syncthreads();

        // S = (Q K^T) * scale
        float s[4][4];
#pragma unroll
        for (int i = 0; i < 4; i++)
#pragma unroll
            for (int j = 0; j < 4; j++) s[i][j] = 0.f;

#pragma unroll 8
        for (int e = 0; e < 64; e++) {
            float4 q = *reinterpret_cast<const float4*>(&Qs[e * 68 + r0]);
            float4 k = *reinterpret_cast<const float4*>(&Ks[e * 68 + n0]);
            float qv[4] = {q.x, q.y, q.z, q.w};
            float kv[4] = {k.x, k.y, k.z, k.w};
#pragma unroll
            for (int i = 0; i < 4; i++)
#pragma unroll
                for (int j = 0; j < 4; j++)
                    s[i][j] = fmaf(qv[i], kv[j], s[i][j]);
        }

        const float scale = 0.125f;   // HS^-0.5
#pragma unroll
        for (int i = 0; i < 4; i++)
#pragma unroll
            for (int j = 0; j < 4; j++) s[i][j] *= scale;

        if (jt == it) {  // causal mask on diagonal tile
#pragma unroll
            for (int i = 0; i < 4; i++)
#pragma unroll
                for (int j = 0; j < 4; j++)
                    if (n0 + j > r0 + i) s[i][j] = -1e30f;
        }

        // online softmax update
        float p[4][4];
#pragma unroll
        for (int i = 0; i < 4; i++) {
            float mx = fmaxf(fmaxf(s[i][0], s[i][1]), fmaxf(s[i][2], s[i][3]));
#pragma unroll
            for (int o = 1; o < 16; o <<= 1)
                mx = fmaxf(mx, __shfl_xor_sync(0xffffffffu, mx, o));
            float mnew = fmaxf(m_r[i], mx);
            float sc = __expf(m_r[i] - mnew);
            float rs = 0.f;
#pragma unroll
            for (int j = 0; j < 4; j++) {
                p[i][j] = __expf(s[i][j] - mnew);
                rs += p[i][j];
            }
#pragma unroll
            for (int o = 1; o < 16; o <<= 1)
                rs += __shfl_xor_sync(0xffffffffu, rs, o);
            l_r[i] = l_r[i] * sc + rs;
#pragma unroll
            for (int j = 0; j < 4; j++) acc[i][j] *= sc;
            m_r[i] = mnew;
        }

        __syncthreads();  // all Ks reads done before overwriting with P
        // write P into Ks buffer: Ps[c][r], stride 68
#pragma unroll
        for (int j = 0; j < 4; j++)
#pragma unroll
            for (int i = 0; i < 4; i++)
                Ks[(n0 + j) * 68 + (r0 + i)] = p[i][j];
        __syncthreads();

        // O += P @ V
#pragma unroll 8
        for (int kk = 0; kk < 64; kk++) {
            float4 pv = *reinterpret_cast<const float4*>(&Ks[kk * 68 + r0]);
            float4 vv = *reinterpret_cast<const float4*>(&Vs[kk * 64 + n0]);
            float pr[4] = {pv.x, pv.y, pv.z, pv.w};
            float vn[4] = {vv.x, vv.y, vv.z, vv.w};
#pragma unroll
            for (int i = 0; i < 4; i++)
#pragma unroll
                for (int j = 0; j < 4; j++)
                    acc[i][j] = fmaf(pr[i], vn[j], acc[i][j]);
        }
    }

    // normalize + write to concat-head layout g_att[b, t, h*HS + e]
#pragma unroll
    for (int i = 0; i < 4; i++) {
        float inv = 1.f / l_r[i];
        size_t row = (size_t)b * TT + (size_t)it * 64 + r0 + i;
#pragma unroll
        for (int j = 0; j < 4; j++)
            g_att[row * DD + (size_t)h * HSS + n0 + j] = acc[i][j] * inv;
    }
}

// ---------------------------------------------------------------------------
// Output projection: out[B*T, D] = g_att[B*T, D] @ Wo[D, D] + bo
// grid: (B*T/128, D/64)
// ---------------------------------------------------------------------------
__global__ void proj_kernel(const float* __restrict__ Wo,
                            const float* __restrict__ bo,
                            float* __restrict__ out)
{
    const int mt = blockIdx.x;
    const int nt = blockIdx.y;
    const float* A  = g_att + (size_t)mt * 128 * DD;
    const float* Bm = Wo + (size_t)nt * 64;
    float* C = out + (size_t)mt * 128 * DD + (size_t)nt * 64;
    gemm_mma_128x64(A, DD, Bm, DD, C, DD, DD, bo + nt * 64);
}

extern "C" void kernel_launch(void* const* d_in, const int* in_sizes, int n_in,
                              void* d_out, int out_size)
{
    const float* x  = (const float*)d_in[0];
    const float* Wq = (const float*)d_in[1];
    const float* Wk = (const float*)d_in[2];
    const float* Wv = (const float*)d_in[3];
    const float* Wo = (const float*)d_in[4];
    const float* bo = (const float*)d_in[5];
    float* out = (float*)d_out;

    cudaFuncSetAttribute(attn_kernel,
                         cudaFuncAttributeMaxDynamicSharedMemorySize, ATTN_SMEM);

    dim3 g1(TT / 128, HH, BB * 3);
    qkv_kernel<<<g1, 256>>>(x, Wq, Wk, Wv);

    dim3 g2(TT / 64, BB * HH);
    attn_kernel<<<g2, 256, ATTN_SMEM>>>();

    dim3 g3((BB * TT) / 128, DD / 64);
    proj_kernel<<<g3, 256>>>(Wo, bo, out);
}

// round 3
// speedup vs baseline: 4.5034x; 1.5568x over previous
#include <cuda_runtime.h>
#include <math.h>

#define BB 4
#define TT 1024
#define DD 1024
#define HH 16
#define HSS 64

// Scratch (no cudaMalloc allowed)
__device__ float g_q[BB*HH*TT*HSS];
__device__ float g_k[BB*HH*TT*HSS];
__device__ float g_v[BB*HH*TT*HSS];
__device__ float g_att[BB*TT*DD];   // concat-head attention output [B*T, H*HS]

// ---------------------------------------------------------------------------
// tf32 helpers
// ---------------------------------------------------------------------------
__device__ __forceinline__ unsigned f2tf(float f) {
    unsigned r;
    asm("cvt.rna.tf32.f32 %0, %1;" : "=r"(r) : "f"(f));
    return r;
}
__device__ __forceinline__ float tf32r(float f) {
    return __uint_as_float(f2tf(f));
}

__device__ __forceinline__ void mma8(float* d, const unsigned* a, const unsigned* b) {
    asm volatile(
        "mma.sync.aligned.m16n8k8.row.col.f32.tf32.tf32.f32 "
        "{%0,%1,%2,%3}, {%4,%5,%6,%7}, {%8,%9}, {%0,%1,%2,%3};"
        : "+f"(d[0]), "+f"(d[1]), "+f"(d[2]), "+f"(d[3])
        : "r"(a[0]), "r"(a[1]), "r"(a[2]), "r"(a[3]),
          "r"(b[0]), "r"(b[1]));
}

// ---------------------------------------------------------------------------
// Tensor-core GEMM tile: C[128,64] = A[128,K] @ Bm[K,64] (+bias), tf32 mma.
// 256 threads = 8 warps in 4(m) x 2(n); warp tile 32x32; frag m16n8k8.
// ---------------------------------------------------------------------------
__device__ __forceinline__ void gemm_mma_128x64(
    const float* __restrict__ A, int lda,
    const float* __restrict__ Bm, int ldb,
    float* __restrict__ C, int ldc,
    int K, const float* __restrict__ bias)
{
    __shared__ unsigned As[128 * 36];
    __shared__ unsigned Bs[32 * 72];

    const int tid  = threadIdx.x;
    const int lane = tid & 31;
    const int warp = tid >> 5;
    const int wm   = warp >> 1;     // 0..3
    const int wn   = warp & 1;      // 0..1
    const int lq   = lane >> 2;     // 0..7
    const int lr   = lane & 3;      // 0..3

    float acc[2][4][4];
#pragma unroll
    for (int mf = 0; mf < 2; mf++)
#pragma unroll
        for (int nf = 0; nf < 4; nf++)
#pragma unroll
            for (int j = 0; j < 4; j++) acc[mf][nf][j] = 0.f;

    for (int k0 = 0; k0 < K; k0 += 32) {
#pragma unroll
        for (int i = 0; i < 4; i++) {
            int l   = tid + i * 256;
            int row = l >> 3;
            int k4  = l & 7;
            float4 v = *reinterpret_cast<const float4*>(&A[(size_t)row * lda + k0 + k4 * 4]);
            unsigned* p = &As[row * 36 + k4 * 4];
            p[0] = f2tf(v.x); p[1] = f2tf(v.y); p[2] = f2tf(v.z); p[3] = f2tf(v.w);
        }
#pragma unroll
        for (int i = 0; i < 2; i++) {
            int l  = tid + i * 256;
            int kr = l >> 4;
            int n4 = l & 15;
            float4 v = *reinterpret_cast<const float4*>(&Bm[(size_t)(k0 + kr) * ldb + n4 * 4]);
            unsigned* p = &Bs[kr * 72 + n4 * 4];
            p[0] = f2tf(v.x); p[1] = f2tf(v.y); p[2] = f2tf(v.z); p[3] = f2tf(v.w);
        }
        __syncthreads();

#pragma unroll
        for (int kk = 0; kk < 4; kk++) {
            const int kc = kk * 8 + lr;
            unsigned a[2][4], b[4][2];
#pragma unroll
            for (int mf = 0; mf < 2; mf++) {
                int mr = wm * 32 + mf * 16 + lq;
                a[mf][0] = As[mr * 36 + kc];
                a[mf][1] = As[(mr + 8) * 36 + kc];
                a[mf][2] = As[mr * 36 + kc + 4];
                a[mf][3] = As[(mr + 8) * 36 + kc + 4];
            }
#pragma unroll
            for (int nf = 0; nf < 4; nf++) {
                int nc = wn * 32 + nf * 8 + lq;
                b[nf][0] = Bs[kc * 72 + nc];
                b[nf][1] = Bs[(kc + 4) * 72 + nc];
            }
#pragma unroll
            for (int mf = 0; mf < 2; mf++)
#pragma unroll
                for (int nf = 0; nf < 4; nf++)
                    mma8(acc[mf][nf], a[mf], b[nf]);
        }
        __syncthreads();
    }

#pragma unroll
    for (int mf = 0; mf < 2; mf++) {
#pragma unroll
        for (int nf = 0; nf < 4; nf++) {
            int row = wm * 32 + mf * 16 + lq;
            int col = wn * 32 + nf * 8 + 2 * lr;
            float b0 = bias ? bias[col] : 0.f;
            float b1 = bias ? bias[col + 1] : 0.f;
            C[(size_t)row * ldc + col]           = acc[mf][nf][0] + b0;
            C[(size_t)row * ldc + col + 1]       = acc[mf][nf][1] + b1;
            C[(size_t)(row + 8) * ldc + col]     = acc[mf][nf][2] + b0;
            C[(size_t)(row + 8) * ldc + col + 1] = acc[mf][nf][3] + b1;
        }
    }
}

// ---------------------------------------------------------------------------
// QKV projection
// ---------------------------------------------------------------------------
__global__ void qkv_kernel(const float* __restrict__ x,
                           const float* __restrict__ Wq,
                           const float* __restrict__ Wk,
                           const float* __restrict__ Wv)
{
    const int mt = blockIdx.x;
    const int h  = blockIdx.y;
    const int z  = blockIdx.z;
    const int b  = z / 3;
    const int which = z % 3;

    const float* A = x + (size_t)b * TT * DD + (size_t)mt * 128 * DD;
    const float* W = (which == 0 ? Wq : which == 1 ? Wk : Wv) + (size_t)h * DD * HSS;
    float* Cb = (which == 0 ? g_q : which == 1 ? g_k : g_v)
                + ((size_t)(b * HH + h) * TT + (size_t)mt * 128) * HSS;

    gemm_mma_128x64(A, DD, W, HSS, Cb, HSS, DD, nullptr);
}

// ---------------------------------------------------------------------------
// Causal flash attention, tf32 tensor cores.
// Block = 128 threads (4 warps), q-tile 64 rows; warp w owns rows [16w,16w+16).
// kv tiles of 64. S = Q K^T via mma; P bounced through smem (per-warp rows);
// O += P V via mma.
// Smem: Qs[64][68], Ks[64][68], Vs[64][72], Ps[64][68]  (tf32-rounded floats)
// ---------------------------------------------------------------------------
#define ATTN_SMEM ((64*68 + 64*68 + 64*72 + 64*68) * 4)

__global__ void attn_kernel()
{
    extern __shared__ float sm[];
    float* Qs = sm;                 // [m][e] stride 68
    float* Ks = Qs + 64 * 68;       // [n][e] stride 68
    float* Vs = Ks + 64 * 68;       // [k][n] stride 72
    float* Ps = Vs + 64 * 72;       // [m][k] stride 68

    const int it = blockIdx.x;      // query tile (64 rows)
    const int bh = blockIdx.y;      // b*H + h
    const int b = bh >> 4, h = bh & 15;

    const float* Q  = g_q + (size_t)bh * TT * HSS + (size_t)it * 64 * HSS;
    const float* Kg = g_k + (size_t)bh * TT * HSS;
    const float* Vg = g_v + (size_t)bh * TT * HSS;

    const int tid  = threadIdx.x;
    const int lane = tid & 31;
    const int warp = tid >> 5;
    const int lq   = lane >> 2;     // 0..7
    const int lr   = lane & 3;      // 0..3
    const int mrow = warp * 16 + lq;   // local rows mrow, mrow+8

    // Load Q tile (tf32-rounded)
#pragma unroll
    for (int i = 0; i < 8; i++) {
        int l = tid + i * 128;        // 0..1023 float4 slots
        int row = l >> 4;             // 0..63
        int c4  = l & 15;             // 0..15
        float4 v = *reinterpret_cast<const float4*>(&Q[(size_t)row * HSS + c4 * 4]);
        float4 t = make_float4(tf32r(v.x), tf32r(v.y), tf32r(v.z), tf32r(v.w));
        *reinterpret_cast<float4*>(&Qs[row * 68 + c4 * 4]) = t;
    }

    float m0 = -1e30f, m1 = -1e30f, l0 = 0.f, l1 = 0.f;
    float o[8][4];
#pragma unroll
    for (int j = 0; j < 8; j++)
#pragma unroll
        for (int c = 0; c < 4; c++) o[j][c] = 0.f;

    const int ntiles = it + 1;
    for (int jt = 0; jt < ntiles; jt++) {
        __syncthreads();   // prev-iter Ks/Vs reads done; also Q visibility on jt==0
        const float* Kt = Kg + (size_t)jt * 64 * HSS;
        const float* Vt = Vg + (size_t)jt * 64 * HSS;
#pragma unroll
        for (int i = 0; i < 8; i++) {
            int l = tid + i * 128;
            int row = l >> 4;
            int c4  = l & 15;
            float4 kv = *reinterpret_cast<const float4*>(&Kt[(size_t)row * HSS + c4 * 4]);
            *reinterpret_cast<float4*>(&Ks[row * 68 + c4 * 4]) =
                make_float4(tf32r(kv.x), tf32r(kv.y), tf32r(kv.z), tf32r(kv.w));
            float4 vv = *reinterpret_cast<const float4*>(&Vt[(size_t)row * HSS + c4 * 4]);
            *reinterpret_cast<float4*>(&Vs[row * 72 + c4 * 4]) =
                make_float4(tf32r(vv.x), tf32r(vv.y), tf32r(vv.z), tf32r(vv.w));
        }
        __syncthreads();

        // ---- S = Q K^T (warp rows mrow..)
        float s[8][4];
#pragma unroll
        for (int j = 0; j < 8; j++)
#pragma unroll
            for (int c = 0; c < 4; c++) s[j][c] = 0.f;

#pragma unroll
        for (int ke = 0; ke < 8; ke++) {
            const int kc = ke * 8 + lr;
            unsigned a[4];
            a[0] = __float_as_uint(Qs[mrow * 68 + kc]);
            a[1] = __float_as_uint(Qs[(mrow + 8) * 68 + kc]);
            a[2] = __float_as_uint(Qs[mrow * 68 + kc + 4]);
            a[3] = __float_as_uint(Qs[(mrow + 8) * 68 + kc + 4]);
#pragma unroll
            for (int j = 0; j < 8; j++) {
                unsigned bfr[2];
                bfr[0] = __float_as_uint(Ks[(j * 8 + lq) * 68 + kc]);
                bfr[1] = __float_as_uint(Ks[(j * 8 + lq) * 68 + kc + 4]);
                mma8(s[j], a, bfr);
            }
        }

        const float scale = 0.125f;
#pragma unroll
        for (int j = 0; j < 8; j++)
#pragma unroll
            for (int c = 0; c < 4; c++) s[j][c] *= scale;

        if (jt == it) {  // causal mask on diagonal tile
            int r0g = mrow, r1g = mrow + 8;
#pragma unroll
            for (int j = 0; j < 8; j++) {
                int c0 = j * 8 + 2 * lr, c1 = c0 + 1;
                if (c0 > r0g) s[j][0] = -1e30f;
                if (c1 > r0g) s[j][1] = -1e30f;
                if (c0 > r1g) s[j][2] = -1e30f;
                if (c1 > r1g) s[j][3] = -1e30f;
            }
        }

        // ---- online softmax (rows mrow and mrow+8)
        float mx0 = -1e30f, mx1 = -1e30f;
#pragma unroll
        for (int j = 0; j < 8; j++) {
            mx0 = fmaxf(mx0, fmaxf(s[j][0], s[j][1]));
            mx1 = fmaxf(mx1, fmaxf(s[j][2], s[j][3]));
        }
        mx0 = fmaxf(mx0, __shfl_xor_sync(0xffffffffu, mx0, 1));
        mx0 = fmaxf(mx0, __shfl_xor_sync(0xffffffffu, mx0, 2));
        mx1 = fmaxf(mx1, __shfl_xor_sync(0xffffffffu, mx1, 1));
        mx1 = fmaxf(mx1, __shfl_xor_sync(0xffffffffu, mx1, 2));

        float mn0 = fmaxf(m0, mx0), mn1 = fmaxf(m1, mx1);
        float f0 = __expf(m0 - mn0), f1 = __expf(m1 - mn1);

        float rs0 = 0.f, rs1 = 0.f;
        float p[8][4];
#pragma unroll
        for (int j = 0; j < 8; j++) {
            p[j][0] = __expf(s[j][0] - mn0);
            p[j][1] = __expf(s[j][1] - mn0);
            p[j][2] = __expf(s[j][2] - mn1);
            p[j][3] = __expf(s[j][3] - mn1);
            rs0 += p[j][0] + p[j][1];
            rs1 += p[j][2] + p[j][3];
        }
        rs0 += __shfl_xor_sync(0xffffffffu, rs0, 1);
        rs0 += __shfl_xor_sync(0xffffffffu, rs0, 2);
        rs1 += __shfl_xor_sync(0xffffffffu, rs1, 1);
        rs1 += __shfl_xor_sync(0xffffffffu, rs1, 2);

        l0 = l0 * f0 + rs0;
        l1 = l1 * f1 + rs1;
        m0 = mn0; m1 = mn1;
#pragma unroll
        for (int j = 0; j < 8; j++) {
            o[j][0] *= f0; o[j][1] *= f0;
            o[j][2] *= f1; o[j][3] *= f1;
        }

        // ---- P -> smem (own warp rows only), tf32-rounded
#pragma unroll
        for (int j = 0; j < 8; j++) {
            int cb = j * 8 + 2 * lr;
            *reinterpret_cast<float2*>(&Ps[mrow * 68 + cb]) =
                make_float2(tf32r(p[j][0]), tf32r(p[j][1]));
            *reinterpret_cast<float2*>(&Ps[(mrow + 8) * 68 + cb]) =
                make_float2(tf32r(p[j][2]), tf32r(p[j][3]));
        }
        __syncwarp();

        // ---- O += P V
#pragma unroll
        for (int kk = 0; kk < 8; kk++) {
            const int kc = kk * 8 + lr;
            unsigned a[4];
            a[0] = __float_as_uint(Ps[mrow * 68 + kc]);
            a[1] = __float_as_uint(Ps[(mrow + 8) * 68 + kc]);
            a[2] = __float_as_uint(Ps[mrow * 68 + kc + 4]);
            a[3] = __float_as_uint(Ps[(mrow + 8) * 68 + kc + 4]);
#pragma unroll
            for (int j = 0; j < 8; j++) {
                unsigned bfr[2];
                bfr[0] = __float_as_uint(Vs[kc * 72 + j * 8 + lq]);
                bfr[1] = __float_as_uint(Vs[(kc + 4) * 72 + j * 8 + lq]);
                mma8(o[j], a, bfr);
            }
        }
    }

    // normalize + write to concat-head layout g_att[b, t, h*HS + e]
    float inv0 = 1.f / l0, inv1 = 1.f / l1;
    size_t row0 = (size_t)b * TT + (size_t)it * 64 + mrow;
    size_t row1 = row0 + 8;
#pragma unroll
    for (int j = 0; j < 8; j++) {
        int cb = h * HSS + j * 8 + 2 * lr;
        *reinterpret_cast<float2*>(&g_att[row0 * DD + cb]) =
            make_float2(o[j][0] * inv0, o[j][1] * inv0);
        *reinterpret_cast<float2*>(&g_att[row1 * DD + cb]) =
            make_float2(o[j][2] * inv1, o[j][3] * inv1);
    }
}

// ---------------------------------------------------------------------------
// Output projection: out[B*T, D] = g_att[B*T, D] @ Wo[D, D] + bo
// ---------------------------------------------------------------------------
__global__ void proj_kernel(const float* __restrict__ Wo,
                            const float* __restrict__ bo,
                            float* __restrict__ out)
{
    const int mt = blockIdx.x;
    const int nt = blockIdx.y;
    const float* A  = g_att + (size_t)mt * 128 * DD;
    const float* Bm = Wo + (size_t)nt * 64;
    float* C = out + (size_t)mt * 128 * DD + (size_t)nt * 64;
    gemm_mma_128x64(A, DD, Bm, DD, C, DD, DD, bo + nt * 64);
}

extern "C" void kernel_launch(void* const* d_in, const int* in_sizes, int n_in,
                              void* d_out, int out_size)
{
    const float* x  = (const float*)d_in[0];
    const float* Wq = (const float*)d_in[1];
    const float* Wk = (const float*)d_in[2];
    const float* Wv = (const float*)d_in[3];
    const float* Wo = (const float*)d_in[4];
    const float* bo = (const float*)d_in[5];
    float* out = (float*)d_out;

    cudaFuncSetAttribute(attn_kernel,
                         cudaFuncAttributeMaxDynamicSharedMemorySize, ATTN_SMEM);

    dim3 g1(TT / 128, HH, BB * 3);
    qkv_kernel<<<g1, 256>>>(x, Wq, Wk, Wv);

    dim3 g2(TT / 64, BB * HH);
    attn_kernel<<<g2, 128, ATTN_SMEM>>>();

    dim3 g3((BB * TT) / 128, DD / 64);
    proj_kernel<<<g3, 256>>>(Wo, bo, out);
}

// round 4
// speedup vs baseline: 5.2210x; 1.1593x over previous
#include <cuda_runtime.h>
#include <math.h>

#define BB 4
#define TT 1024
#define DD 1024
#define HH 16
#define HSS 64

// Scratch (no cudaMalloc allowed)
__device__ float g_q[BB*HH*TT*HSS];
__device__ float g_k[BB*HH*TT*HSS];
__device__ float g_v[BB*HH*TT*HSS];
__device__ float g_att[BB*TT*DD];   // concat-head attention output [B*T, H*HS]

// ---------------------------------------------------------------------------
// tf32 helpers
// ---------------------------------------------------------------------------
__device__ __forceinline__ unsigned f2tf(float f) {
    unsigned r;
    asm("cvt.rna.tf32.f32 %0, %1;" : "=r"(r) : "f"(f));
    return r;
}
__device__ __forceinline__ float tf32r(float f) {
    return __uint_as_float(f2tf(f));
}

__device__ __forceinline__ void mma8(float* d, const unsigned* a, const unsigned* b) {
    asm volatile(
        "mma.sync.aligned.m16n8k8.row.col.f32.tf32.tf32.f32 "
        "{%0,%1,%2,%3}, {%4,%5,%6,%7}, {%8,%9}, {%0,%1,%2,%3};"
        : "+f"(d[0]), "+f"(d[1]), "+f"(d[2]), "+f"(d[3])
        : "r"(a[0]), "r"(a[1]), "r"(a[2]), "r"(a[3]),
          "r"(b[0]), "r"(b[1]));
}

// ---------------------------------------------------------------------------
// Shared 128x128 GEMM machinery: 8 warps = 2(m) x 4(n); warp tile 64x32.
// As[m][36]  (bank = 4m+k  -> conflict-free frag loads)
// Bs[k][136] (bank = 8k+n  -> conflict-free frag loads)
// ---------------------------------------------------------------------------
#define AS_STRIDE 36
#define BS_STRIDE 136

__device__ __forceinline__ void mma_block_step(
    const unsigned* __restrict__ As, const unsigned* __restrict__ Bs,
    float acc[4][4][4], int wm, int wn, int lq, int lr)
{
#pragma unroll
    for (int kk = 0; kk < 4; kk++) {
        const int kc = kk * 8 + lr;
        unsigned a[4][4];
#pragma unroll
        for (int mf = 0; mf < 4; mf++) {
            int mr = wm * 64 + mf * 16 + lq;
            a[mf][0] = As[mr * AS_STRIDE + kc];
            a[mf][1] = As[(mr + 8) * AS_STRIDE + kc];
            a[mf][2] = As[mr * AS_STRIDE + kc + 4];
            a[mf][3] = As[(mr + 8) * AS_STRIDE + kc + 4];
        }
        unsigned b[4][2];
#pragma unroll
        for (int nf = 0; nf < 4; nf++) {
            int nc = wn * 32 + nf * 8 + lq;
            b[nf][0] = Bs[kc * BS_STRIDE + nc];
            b[nf][1] = Bs[(kc + 4) * BS_STRIDE + nc];
        }
#pragma unroll
        for (int mf = 0; mf < 4; mf++)
#pragma unroll
            for (int nf = 0; nf < 4; nf++)
                mma8(acc[mf][nf], a[mf], b[nf]);
    }
}

// Load A tile [128 x 32] (row-major, lda) into As (tf32)
__device__ __forceinline__ void load_a_tile(
    unsigned* __restrict__ As, const float* __restrict__ A, int lda, int k0, int tid)
{
#pragma unroll
    for (int i = 0; i < 4; i++) {
        int l   = tid + i * 256;
        int row = l >> 3;
        int k4  = l & 7;
        float4 v = *reinterpret_cast<const float4*>(&A[(size_t)row * lda + k0 + k4 * 4]);
        unsigned* p = &As[row * AS_STRIDE + k4 * 4];
        p[0] = f2tf(v.x); p[1] = f2tf(v.y); p[2] = f2tf(v.z); p[3] = f2tf(v.w);
    }
}

// ---------------------------------------------------------------------------
// Fused QKV projection as one logical GEMM [4096 x 3072 x 1024].
// grid (32, 24): nt 0..7 -> Q, 8..15 -> K, 16..23 -> V; each n-tile = 2 heads.
// ---------------------------------------------------------------------------
__global__ __launch_bounds__(256, 2) void qkv_kernel(
    const float* __restrict__ x,
    const float* __restrict__ Wq,
    const float* __restrict__ Wk,
    const float* __restrict__ Wv)
{
    __shared__ unsigned As[128 * AS_STRIDE];
    __shared__ unsigned Bs[32 * BS_STRIDE];

    const int mt = blockIdx.x;           // 0..31 (rows of x: b*T+t)
    const int nt = blockIdx.y;           // 0..23
    const int which = nt >> 3;
    const int h0 = (nt & 7) * 2;

    const float* W = (which == 0 ? Wq : which == 1 ? Wk : Wv);
    float* dst     = (which == 0 ? g_q : which == 1 ? g_k : g_v);
    const float* A = x + (size_t)mt * 128 * DD;

    const int tid  = threadIdx.x;
    const int lane = tid & 31;
    const int warp = tid >> 5;
    const int wm   = warp >> 2;          // 0..1
    const int wn   = warp & 3;           // 0..3
    const int lq   = lane >> 2;
    const int lr   = lane & 3;

    float acc[4][4][4];
#pragma unroll
    for (int mf = 0; mf < 4; mf++)
#pragma unroll
        for (int nf = 0; nf < 4; nf++)
#pragma unroll
            for (int j = 0; j < 4; j++) acc[mf][nf][j] = 0.f;

    for (int k0 = 0; k0 < DD; k0 += 32) {
        load_a_tile(As, A, DD, k0, tid);
        // B tile [32 x 128]: col n -> head h0 + (n>>6), hs = n&63
#pragma unroll
        for (int i = 0; i < 4; i++) {
            int l  = tid + i * 256;
            int kr = l >> 5;             // 0..31
            int n  = (l & 31) * 4;       // 0..124
            int h  = h0 + (n >> 6);
            int hs = n & 63;
            float4 v = *reinterpret_cast<const float4*>(
                &W[(size_t)h * DD * HSS + (size_t)(k0 + kr) * HSS + hs]);
            unsigned* p = &Bs[kr * BS_STRIDE + n];
            p[0] = f2tf(v.x); p[1] = f2tf(v.y); p[2] = f2tf(v.z); p[3] = f2tf(v.w);
        }
        __syncthreads();
        mma_block_step(As, Bs, acc, wm, wn, lq, lr);
        __syncthreads();
    }

    // Epilogue: write to g_{q,k,v}[(b*H+h)*T*HS + t*HS + hs]
#pragma unroll
    for (int mf = 0; mf < 4; mf++) {
#pragma unroll
        for (int nf = 0; nf < 4; nf++) {
            int row = wm * 64 + mf * 16 + lq;
            int col = wn * 32 + nf * 8 + 2 * lr;
            int h   = h0 + (col >> 6);
            int hs  = col & 63;
#pragma unroll
            for (int half = 0; half < 2; half++) {
                int gr = mt * 128 + row + half * 8;
                int b = gr >> 10, t = gr & 1023;
                float* drow = dst + ((size_t)(b * HH + h) * TT + t) * HSS + hs;
                *reinterpret_cast<float2*>(drow) =
                    make_float2(acc[mf][nf][half * 2], acc[mf][nf][half * 2 + 1]);
            }
        }
    }
}

// ---------------------------------------------------------------------------
// Output projection: out[4096, 1024] = g_att @ Wo + bo.  grid (32, 8).
// ---------------------------------------------------------------------------
__global__ __launch_bounds__(256, 2) void proj_kernel(
    const float* __restrict__ Wo,
    const float* __restrict__ bo,
    float* __restrict__ out)
{
    __shared__ unsigned As[128 * AS_STRIDE];
    __shared__ unsigned Bs[32 * BS_STRIDE];

    const int mt = blockIdx.x;           // 0..31
    const int nt = blockIdx.y;           // 0..7

    const float* A = g_att + (size_t)mt * 128 * DD;

    const int tid  = threadIdx.x;
    const int lane = tid & 31;
    const int warp = tid >> 5;
    const int wm   = warp >> 2;
    const int wn   = warp & 3;
    const int lq   = lane >> 2;
    const int lr   = lane & 3;

    float acc[4][4][4];
#pragma unroll
    for (int mf = 0; mf < 4; mf++)
#pragma unroll
        for (int nf = 0; nf < 4; nf++)
#pragma unroll
            for (int j = 0; j < 4; j++) acc[mf][nf][j] = 0.f;

    for (int k0 = 0; k0 < DD; k0 += 32) {
        load_a_tile(As, A, DD, k0, tid);
#pragma unroll
        for (int i = 0; i < 4; i++) {
            int l  = tid + i * 256;
            int kr = l >> 5;
            int n  = (l & 31) * 4;
            float4 v = *reinterpret_cast<const float4*>(
                &Wo[(size_t)(k0 + kr) * DD + nt * 128 + n]);
            unsigned* p = &Bs[kr * BS_STRIDE + n];
            p[0] = f2tf(v.x); p[1] = f2tf(v.y); p[2] = f2tf(v.z); p[3] = f2tf(v.w);
        }
        __syncthreads();
        mma_block_step(As, Bs, acc, wm, wn, lq, lr);
        __syncthreads();
    }

#pragma unroll
    for (int mf = 0; mf < 4; mf++) {
#pragma unroll
        for (int nf = 0; nf < 4; nf++) {
            int row = wm * 64 + mf * 16 + lq;
            int col = nt * 128 + wn * 32 + nf * 8 + 2 * lr;
            float b0 = bo[col], b1 = bo[col + 1];
            float* C0 = out + (size_t)(mt * 128 + row) * DD + col;
            float* C1 = out + (size_t)(mt * 128 + row + 8) * DD + col;
            *reinterpret_cast<float2*>(C0) =
                make_float2(acc[mf][nf][0] + b0, acc[mf][nf][1] + b1);
            *reinterpret_cast<float2*>(C1) =
                make_float2(acc[mf][nf][2] + b0, acc[mf][nf][3] + b1);
        }
    }
}

// ---------------------------------------------------------------------------
// Causal flash attention, tf32 tensor cores (unchanged from R3).
// ---------------------------------------------------------------------------
#define ATTN_SMEM ((64*68 + 64*68 + 64*72 + 64*68) * 4)

__global__ void attn_kernel()
{
    extern __shared__ float sm[];
    float* Qs = sm;                 // [m][e] stride 68
    float* Ks = Qs + 64 * 68;       // [n][e] stride 68
    float* Vs = Ks + 64 * 68;       // [k][n] stride 72
    float* Ps = Vs + 64 * 72;       // [m][k] stride 68

    const int it = blockIdx.x;
    const int bh = blockIdx.y;
    const int b = bh >> 4, h = bh & 15;

    const float* Q  = g_q + (size_t)bh * TT * HSS + (size_t)it * 64 * HSS;
    const float* Kg = g_k + (size_t)bh * TT * HSS;
    const float* Vg = g_v + (size_t)bh * TT * HSS;

    const int tid  = threadIdx.x;
    const int lane = tid & 31;
    const int warp = tid >> 5;
    const int lq   = lane >> 2;
    const int lr   = lane & 3;
    const int mrow = warp * 16 + lq;

#pragma unroll
    for (int i = 0; i < 8; i++) {
        int l = tid + i * 128;
        int row = l >> 4;
        int c4  = l & 15;
        float4 v = *reinterpret_cast<const float4*>(&Q[(size_t)row * HSS + c4 * 4]);
        *reinterpret_cast<float4*>(&Qs[row * 68 + c4 * 4]) =
            make_float4(tf32r(v.x), tf32r(v.y), tf32r(v.z), tf32r(v.w));
    }

    float m0 = -1e30f, m1 = -1e30f, l0 = 0.f, l1 = 0.f;
    float o[8][4];
#pragma unroll
    for (int j = 0; j < 8; j++)
#pragma unroll
        for (int c = 0; c < 4; c++) o[j][c] = 0.f;

    const int ntiles = it + 1;
    for (int jt = 0; jt < ntiles; jt++) {
        __syncthreads();
        const float* Kt = Kg + (size_t)jt * 64 * HSS;
        const float* Vt = Vg + (size_t)jt * 64 * HSS;
#pragma unroll
        for (int i = 0; i < 8; i++) {
            int l = tid + i * 128;
            int row = l >> 4;
            int c4  = l & 15;
            float4 kv = *reinterpret_cast<const float4*>(&Kt[(size_t)row * HSS + c4 * 4]);
            *reinterpret_cast<float4*>(&Ks[row * 68 + c4 * 4]) =
                make_float4(tf32r(kv.x), tf32r(kv.y), tf32r(kv.z), tf32r(kv.w));
            float4 vv = *reinterpret_cast<const float4*>(&Vt[(size_t)row * HSS + c4 * 4]);
            *reinterpret_cast<float4*>(&Vs[row * 72 + c4 * 4]) =
                make_float4(tf32r(vv.x), tf32r(vv.y), tf32r(vv.z), tf32r(vv.w));
        }
        __syncthreads();

        float s[8][4];
#pragma unroll
        for (int j = 0; j < 8; j++)
#pragma unroll
            for (int c = 0; c < 4; c++) s[j][c] = 0.f;

#pragma unroll
        for (int ke = 0; ke < 8; ke++) {
            const int kc = ke * 8 + lr;
            unsigned a[4];
            a[0] = __float_as_uint(Qs[mrow * 68 + kc]);
            a[1] = __float_as_uint(Qs[(mrow + 8) * 68 + kc]);
            a[2] = __float_as_uint(Qs[mrow * 68 + kc + 4]);
            a[3] = __float_as_uint(Qs[(mrow + 8) * 68 + kc + 4]);
#pragma unroll
            for (int j = 0; j < 8; j++) {
                unsigned bfr[2];
                bfr[0] = __float_as_uint(Ks[(j * 8 + lq) * 68 + kc]);
                bfr[1] = __float_as_uint(Ks[(j * 8 + lq) * 68 + kc + 4]);
                mma8(s[j], a, bfr);
            }
        }

        const float scale = 0.125f;
#pragma unroll
        for (int j = 0; j < 8; j++)
#pragma unroll
            for (int c = 0; c < 4; c++) s[j][c] *= scale;

        if (jt == it) {
            int r0g = mrow, r1g = mrow + 8;
#pragma unroll
            for (int j = 0; j < 8; j++) {
                int c0 = j * 8 + 2 * lr, c1 = c0 + 1;
                if (c0 > r0g) s[j][0] = -1e30f;
                if (c1 > r0g) s[j][1] = -1e30f;
                if (c0 > r1g) s[j][2] = -1e30f;
                if (c1 > r1g) s[j][3] = -1e30f;
            }
        }

        float mx0 = -1e30f, mx1 = -1e30f;
#pragma unroll
        for (int j = 0; j < 8; j++) {
            mx0 = fmaxf(mx0, fmaxf(s[j][0], s[j][1]));
            mx1 = fmaxf(mx1, fmaxf(s[j][2], s[j][3]));
        }
        mx0 = fmaxf(mx0, __shfl_xor_sync(0xffffffffu, mx0, 1));
        mx0 = fmaxf(mx0, __shfl_xor_sync(0xffffffffu, mx0, 2));
        mx1 = fmaxf(mx1, __shfl_xor_sync(0xffffffffu, mx1, 1));
        mx1 = fmaxf(mx1, __shfl_xor_sync(0xffffffffu, mx1, 2));

        float mn0 = fmaxf(m0, mx0), mn1 = fmaxf(m1, mx1);
        float f0 = __expf(m0 - mn0), f1 = __expf(m1 - mn1);

        float rs0 = 0.f, rs1 = 0.f;
        float p[8][4];
#pragma unroll
        for (int j = 0; j < 8; j++) {
            p[j][0] = __expf(s[j][0] - mn0);
            p[j][1] = __expf(s[j][1] - mn0);
            p[j][2] = __expf(s[j][2] - mn1);
            p[j][3] = __expf(s[j][3] - mn1);
            rs0 += p[j][0] + p[j][1];
            rs1 += p[j][2] + p[j][3];
        }
        rs0 += __shfl_xor_sync(0xffffffffu, rs0, 1);
        rs0 += __shfl_xor_sync(0xffffffffu, rs0, 2);
        rs1 += __shfl_xor_sync(0xffffffffu, rs1, 1);
        rs1 += __shfl_xor_sync(0xffffffffu, rs1, 2);

        l0 = l0 * f0 + rs0;
        l1 = l1 * f1 + rs1;
        m0 = mn0; m1 = mn1;
#pragma unroll
        for (int j = 0; j < 8; j++) {
            o[j][0] *= f0; o[j][1] *= f0;
            o[j][2] *= f1; o[j][3] *= f1;
        }

#pragma unroll
        for (int j = 0; j < 8; j++) {
            int cb = j * 8 + 2 * lr;
            *reinterpret_cast<float2*>(&Ps[mrow * 68 + cb]) =
                make_float2(tf32r(p[j][0]), tf32r(p[j][1]));
            *reinterpret_cast<float2*>(&Ps[(mrow + 8) * 68 + cb]) =
                make_float2(tf32r(p[j][2]), tf32r(p[j][3]));
        }
        __syncwarp();

#pragma unroll
        for (int kk = 0; kk < 8; kk++) {
            const int kc = kk * 8 + lr;
            unsigned a[4];
            a[0] = __float_as_uint(Ps[mrow * 68 + kc]);
            a[1] = __float_as_uint(Ps[(mrow + 8) * 68 + kc]);
            a[2] = __float_as_uint(Ps[mrow * 68 + kc + 4]);
            a[3] = __float_as_uint(Ps[(mrow + 8) * 68 + kc + 4]);
#pragma unroll
            for (int j = 0; j < 8; j++) {
                unsigned bfr[2];
                bfr[0] = __float_as_uint(Vs[kc * 72 + j * 8 + lq]);
                bfr[1] = __float_as_uint(Vs[(kc + 4) * 72 + j * 8 + lq]);
                mma8(o[j], a, bfr);
            }
        }
    }

    float inv0 = 1.f / l0, inv1 = 1.f / l1;
    size_t row0 = (size_t)b * TT + (size_t)it * 64 + mrow;
    size_t row1 = row0 + 8;
#pragma unroll
    for (int j = 0; j < 8; j++) {
        int cb = h * HSS + j * 8 + 2 * lr;
        *reinterpret_cast<float2*>(&g_att[row0 * DD + cb]) =
            make_float2(o[j][0] * inv0, o[j][1] * inv0);
        *reinterpret_cast<float2*>(&g_att[row1 * DD + cb]) =
            make_float2(o[j][2] * inv1, o[j][3] * inv1);
    }
}

extern "C" void kernel_launch(void* const* d_in, const int* in_sizes, int n_in,
                              void* d_out, int out_size)
{
    const float* x  = (const float*)d_in[0];
    const float* Wq = (const float*)d_in[1];
    const float* Wk = (const float*)d_in[2];
    const float* Wv = (const float*)d_in[3];
    const float* Wo = (const float*)d_in[4];
    const float* bo = (const float*)d_in[5];
    float* out = (float*)d_out;

    cudaFuncSetAttribute(attn_kernel,
                         cudaFuncAttributeMaxDynamicSharedMemorySize, ATTN_SMEM);

    dim3 g1((BB * TT) / 128, 24);
    qkv_kernel<<<g1, 256>>>(x, Wq, Wk, Wv);

    dim3 g2(TT / 64, BB * HH);
    attn_kernel<<<g2, 128, ATTN_SMEM>>>();

    dim3 g3((BB * TT) / 128, DD / 128);
    proj_kernel<<<g3, 256>>>(Wo, bo, out);
}